// round 17
// baseline (speedup 1.0000x reference)
#include <cuda_runtime.h>
#include <cuda_fp16.h>
#include <cstdint>
#include <math.h>

#define DIM   4096
#define NH    32
#define HD    128
#define BSZ   2
#define SEQ   2048

// ---------------- scratch (__device__ globals; no allocs allowed) ----------
__device__ __half g_q[BSZ*SEQ*DIM];
__device__ __half g_k[BSZ*SEQ*DIM];
__device__ __half g_v[BSZ*SEQ*DIM];
__device__ float  g_cos[SEQ*(HD/2)];
__device__ float  g_sin[SEQ*(HD/2)];

__device__ __half g_x16[DIM*DIM];
__device__ __half g_wq16[DIM*DIM];
__device__ __half g_wk16[DIM*DIM];
__device__ __half g_wv16[DIM*DIM];
__device__ __half g_wo16[DIM*DIM];
__device__ __half g_a16[DIM*DIM];

// ---------------- base-ISA helpers (compute_103-safe) ----------------------
__device__ __forceinline__ uint32_t smem_u32(const void* p) {
    uint32_t a;
    asm("{ .reg .u64 t; cvta.to.shared.u64 t, %1; cvt.u32.u64 %0, t; }" : "=r"(a) : "l"(p));
    return a;
}
__device__ __forceinline__ void cpa16(uint32_t saddr, const void* g) {
    asm volatile("cp.async.cg.shared.global [%0], [%1], 16;" :: "r"(saddr), "l"(g));
}
__device__ __forceinline__ void ldsm4(uint32_t* r, uint32_t addr) {
    asm volatile("ldmatrix.sync.aligned.m8n8.x4.shared.b16 {%0,%1,%2,%3}, [%4];"
        : "=r"(r[0]), "=r"(r[1]), "=r"(r[2]), "=r"(r[3]) : "r"(addr));
}
__device__ __forceinline__ void ldsm4t(uint32_t* r, uint32_t addr) {
    asm volatile("ldmatrix.sync.aligned.m8n8.x4.trans.shared.b16 {%0,%1,%2,%3}, [%4];"
        : "=r"(r[0]), "=r"(r[1]), "=r"(r[2]), "=r"(r[3]) : "r"(addr));
}
__device__ __forceinline__ void mma_f16(float* c, const uint32_t* a,
                                        uint32_t b0, uint32_t b1) {
    asm volatile("mma.sync.aligned.m16n8k16.row.col.f32.f16.f16.f32 "
        "{%0,%1,%2,%3}, {%4,%5,%6,%7}, {%8,%9}, {%0,%1,%2,%3};"
        : "+f"(c[0]), "+f"(c[1]), "+f"(c[2]), "+f"(c[3])
        : "r"(a[0]), "r"(a[1]), "r"(a[2]), "r"(a[3]), "r"(b0), "r"(b1));
}
__device__ __forceinline__ uint32_t pack_h2(float a, float b) {
    __half2 h = __floats2half2_rn(a, b);
    return *(uint32_t*)&h;
}
__device__ __forceinline__ uint32_t sw128(uint32_t off) {
    return off ^ ((off >> 3) & 0x70);
}

// ---------------------------------------------------------------------------
// casts
// ---------------------------------------------------------------------------
__global__ void split_act(const float* __restrict__ in, __half* __restrict__ o, int n4)
{
    int i = blockIdx.x * 256 + threadIdx.x;
    if (i >= n4) return;
    float4 v = ((const float4*)in)[i];
    __half2 a = __floats2half2_rn(v.x, v.y);
    __half2 b = __floats2half2_rn(v.z, v.w);
    uint2 pkt = make_uint2(*(uint32_t*)&a, *(uint32_t*)&b);
    ((uint2*)o)[i] = pkt;
}

__global__ void split_wt(const float* __restrict__ in, __half* __restrict__ o, int n4)
{
    int i = blockIdx.x * 256 + threadIdx.x;
    if (i >= n4) return;
    float4 v = ((const float4*)in)[i];
    __half2 a = __floats2half2_rn(v.x * 64.f, v.y * 64.f);
    __half2 b = __floats2half2_rn(v.z * 64.f, v.w * 64.f);
    uint2 pkt = make_uint2(*(uint32_t*)&a, *(uint32_t*)&b);
    ((uint2*)o)[i] = pkt;
}

// ---------------------------------------------------------------------------
// Fused QKV GEMM (NT): one launch, 3072 CTAs.
// blockIdx.x selects {q,k,v} (32 N-tiles each). Same mainloop as gemm_mma.
// ---------------------------------------------------------------------------
#define STAGE_SZ 32768
__global__ void __launch_bounds__(256, 2)
gemm_qkv(const __half* __restrict__ A16,
         const __half* __restrict__ Bq, const __half* __restrict__ Bk,
         const __half* __restrict__ Bv,
         __half* __restrict__ Qo, __half* __restrict__ Ko, __half* __restrict__ Vo,
         float scq, float scn,
         const float* __restrict__ Ct, const float* __restrict__ St)
{
    extern __shared__ char sm[];
    const uint32_t s0 = smem_u32(sm);

    const int tid  = threadIdx.x;
    const int wid  = tid >> 5;
    const int lane = tid & 31;
    const int which = blockIdx.x >> 5;        // 0=q 1=k 2=v
    const int bx = blockIdx.x & 31;
    const int by = blockIdx.y;
    const int warp_m = wid >> 1;
    const int warp_n = wid & 1;

    const __half* B16 = (which == 0) ? Bq : (which == 1) ? Bk : Bv;
    __half* Ch        = (which == 0) ? Qo : (which == 1) ? Ko : Vo;
    const float sc    = (which == 0) ? scq : scn;
    const bool rope   = (which < 2);

    float acc[2][8][4];
#pragma unroll
    for (int t = 0; t < 2; t++)
#pragma unroll
        for (int n = 0; n < 8; n++)
#pragma unroll
            for (int j = 0; j < 4; j++) acc[t][n][j] = 0.0f;

    auto load_stage = [&](int kt, int stage) {
        uint32_t sb = s0 + stage * STAGE_SZ;
#pragma unroll
        for (int i = 0; i < 4; i++) {
            int li = tid + i * 256;
            int r = li >> 3, c = li & 7;
            uint32_t off = sw128((uint32_t)(r * 128 + c * 16));
            cpa16(sb + off,         A16 + (size_t)(by * 128 + r) * 4096 + kt * 64 + c * 8);
            cpa16(sb + 16384 + off, B16 + (size_t)(bx * 128 + r) * 4096 + kt * 64 + c * 8);
        }
        asm volatile("cp.async.commit_group;" ::: "memory");
    };

    const int lrow  = (lane & 7) + ((lane >> 3) & 1) * 8;
    const int khalf = (lane >> 4) * 16;

    const int NT = 4096 / 64;

    load_stage(0, 0);
    load_stage(1, 1);

    int cs = 0, ls = 2;
    for (int kt = 0; kt < NT; kt++) {
        if (kt < NT - 1) asm volatile("cp.async.wait_group 1;" ::: "memory");
        else             asm volatile("cp.async.wait_group 0;" ::: "memory");
        __syncthreads();

        const uint32_t sbase = s0 + cs * STAGE_SZ;
        if (kt + 2 < NT) load_stage(kt + 2, ls);
        cs = (cs == 2) ? 0 : cs + 1;
        ls = (ls == 2) ? 0 : ls + 1;

#pragma unroll
        for (int s = 0; s < 4; s++) {
            uint32_t ah[2][4], bh[4][4];
#pragma unroll
            for (int t = 0; t < 2; t++) {
                uint32_t off = sw128((uint32_t)((warp_m * 32 + t * 16 + lrow) * 128
                                                + khalf + s * 32));
                ldsm4(ah[t], sbase + off);
            }
#pragma unroll
            for (int u = 0; u < 4; u++) {
                uint32_t off = sw128((uint32_t)((warp_n * 64 + u * 16 + lrow) * 128
                                                + khalf + s * 32));
                ldsm4(bh[u], sbase + 16384 + off);
            }
#pragma unroll
            for (int t = 0; t < 2; t++)
#pragma unroll
                for (int u = 0; u < 4; u++)
#pragma unroll
                    for (int j = 0; j < 2; j++)
                        mma_f16(acc[t][u * 2 + j], ah[t], bh[u][j], bh[u][j + 2]);
        }
    }

    const int g  = lane >> 2;
    const int qc = lane & 3;
#pragma unroll
    for (int t = 0; t < 2; t++) {
        const int row = by * 128 + warp_m * 32 + t * 16 + g;
#pragma unroll
        for (int n = 0; n < 8; n++) {
            const int col = bx * 128 + warp_n * 64 + n * 8 + qc * 2;
            float x0 = acc[t][n][0] * sc, x1 = acc[t][n][1] * sc;
            float y0 = acc[t][n][2] * sc, y1 = acc[t][n][3] * sc;
            if (rope) {
                const int jj = (col & 127) >> 1;
                float c0 = Ct[(row & 2047) * 64 + jj];
                float s0 = St[(row & 2047) * 64 + jj];
                float c1 = Ct[((row + 8) & 2047) * 64 + jj];
                float s1 = St[((row + 8) & 2047) * 64 + jj];
                float nx0 = x0 * c0 - x1 * s0, nx1 = x0 * s0 + x1 * c0;
                float ny0 = y0 * c1 - y1 * s1, ny1 = y0 * s1 + y1 * c1;
                x0 = nx0; x1 = nx1; y0 = ny0; y1 = ny1;
            }
            *(__half2*)&Ch[(size_t)row * 4096 + col] = __floats2half2_rn(x0, x1);
            *(__half2*)&Ch[(size_t)(row + 8) * 4096 + col] = __floats2half2_rn(y0, y1);
        }
    }
}

// ---------------------------------------------------------------------------
// out-projection GEMM (NT), fp32 output
// ---------------------------------------------------------------------------
__global__ void __launch_bounds__(256, 2)
gemm_out(const __half* __restrict__ A16, const __half* __restrict__ B16,
         float* __restrict__ Cf, float sc)
{
    extern __shared__ char sm[];
    const uint32_t s0 = smem_u32(sm);

    const int tid  = threadIdx.x;
    const int wid  = tid >> 5;
    const int lane = tid & 31;
    const int bx = blockIdx.x;
    const int by = blockIdx.y;
    const int warp_m = wid >> 1;
    const int warp_n = wid & 1;

    float acc[2][8][4];
#pragma unroll
    for (int t = 0; t < 2; t++)
#pragma unroll
        for (int n = 0; n < 8; n++)
#pragma unroll
            for (int j = 0; j < 4; j++) acc[t][n][j] = 0.0f;

    auto load_stage = [&](int kt, int stage) {
        uint32_t sb = s0 + stage * STAGE_SZ;
#pragma unroll
        for (int i = 0; i < 4; i++) {
            int li = tid + i * 256;
            int r = li >> 3, c = li & 7;
            uint32_t off = sw128((uint32_t)(r * 128 + c * 16));
            cpa16(sb + off,         A16 + (size_t)(by * 128 + r) * 4096 + kt * 64 + c * 8);
            cpa16(sb + 16384 + off, B16 + (size_t)(bx * 128 + r) * 4096 + kt * 64 + c * 8);
        }
        asm volatile("cp.async.commit_group;" ::: "memory");
    };

    const int lrow  = (lane & 7) + ((lane >> 3) & 1) * 8;
    const int khalf = (lane >> 4) * 16;

    const int NT = 4096 / 64;

    load_stage(0, 0);
    load_stage(1, 1);

    int cs = 0, ls = 2;
    for (int kt = 0; kt < NT; kt++) {
        if (kt < NT - 1) asm volatile("cp.async.wait_group 1;" ::: "memory");
        else             asm volatile("cp.async.wait_group 0;" ::: "memory");
        __syncthreads();

        const uint32_t sbase = s0 + cs * STAGE_SZ;
        if (kt + 2 < NT) load_stage(kt + 2, ls);
        cs = (cs == 2) ? 0 : cs + 1;
        ls = (ls == 2) ? 0 : ls + 1;

#pragma unroll
        for (int s = 0; s < 4; s++) {
            uint32_t ah[2][4], bh[4][4];
#pragma unroll
            for (int t = 0; t < 2; t++) {
                uint32_t off = sw128((uint32_t)((warp_m * 32 + t * 16 + lrow) * 128
                                                + khalf + s * 32));
                ldsm4(ah[t], sbase + off);
            }
#pragma unroll
            for (int u = 0; u < 4; u++) {
                uint32_t off = sw128((uint32_t)((warp_n * 64 + u * 16 + lrow) * 128
                                                + khalf + s * 32));
                ldsm4(bh[u], sbase + 16384 + off);
            }
#pragma unroll
            for (int t = 0; t < 2; t++)
#pragma unroll
                for (int u = 0; u < 4; u++)
#pragma unroll
                    for (int j = 0; j < 2; j++)
                        mma_f16(acc[t][u * 2 + j], ah[t], bh[u][j], bh[u][j + 2]);
        }
    }

    const int g  = lane >> 2;
    const int qc = lane & 3;
#pragma unroll
    for (int t = 0; t < 2; t++) {
        const int row = by * 128 + warp_m * 32 + t * 16 + g;
#pragma unroll
        for (int n = 0; n < 8; n++) {
            const int col = bx * 128 + warp_n * 64 + n * 8 + qc * 2;
            *(float2*)&Cf[(size_t)row * 4096 + col] =
                make_float2(acc[t][n][0] * sc, acc[t][n][1] * sc);
            *(float2*)&Cf[(size_t)(row + 8) * 4096 + col] =
                make_float2(acc[t][n][2] * sc, acc[t][n][3] * sc);
        }
    }
}

// ---------------------------------------------------------------------------
// RoPE table
// ---------------------------------------------------------------------------
__global__ void rope_table(float* ct, float* st)
{
    __shared__ double sinv[64];
    if (threadIdx.x < 64)
        sinv[threadIdx.x] = pow(10000.0, -(double)threadIdx.x / 64.0);
    __syncthreads();

    int idx = blockIdx.x * 256 + threadIdx.x;
    if (idx >= SEQ * (HD / 2)) return;
    int s = idx >> 6;
    int j = idx & 63;
    double a = fmod((double)s * sinv[j], 6.283185307179586477);
    float cf, sf;
    sincosf((float)a, &sf, &cf);
    ct[idx] = cf;
    st[idx] = sf;
}

// ---------------------------------------------------------------------------
// Causal flash attention (frozen from R16): fp16 mma + ldmatrix,
// 128-row q tiles, 2-stage cp.async K/V pipeline.
// ---------------------------------------------------------------------------
#define KVROW 272
#define KVMAT (64 * KVROW)
#define KVSTG (2 * KVMAT)
#define ATTN_SMEM (2 * KVSTG)

__global__ void __launch_bounds__(256)
attn_tc(const __half* __restrict__ Qh, const __half* __restrict__ Kh,
        const __half* __restrict__ Vh, __half* __restrict__ O16)
{
    extern __shared__ char smc[];
    const uint32_t s0 = smem_u32(smc);

    const int tid  = threadIdx.x;
    const int w    = tid >> 5;
    const int lane = tid & 31;
    const int qt = blockIdx.x;
    const int h  = blockIdx.y;
    const int b  = blockIdx.z;
    const int g  = lane >> 2;
    const int qc = lane & 3;

    const uint32_t k_row = (lane & 7) + ((lane >> 4) & 1) * 8;
    const uint32_t k_db  = ((lane >> 3) & 1) * 16;
    const uint32_t v_row = (lane & 7) + ((lane >> 3) & 1) * 8;
    const uint32_t v_db  = ((lane >> 4) & 1) * 16;

    const int q0 = qt * 128 + w * 16;
    const int NKT = 2 * qt + 2;

    auto load_kv = [&](int kt, int stage) {
        uint32_t sb = s0 + stage * KVSTG;
#pragma unroll
        for (int i = 0; i < 4; i++) {
            int li = tid + i * 256;
            int row = li >> 4, c = li & 15;
            size_t gsrc = ((size_t)b * SEQ + kt * 64 + row) * 4096 + h * 128 + c * 8;
            uint32_t soff = (uint32_t)(row * KVROW + c * 16);
            cpa16(sb + soff,         Kh + gsrc);
            cpa16(sb + KVMAT + soff, Vh + gsrc);
        }
        asm volatile("cp.async.commit_group;" ::: "memory");
    };

    uint32_t qa[8][4];
    {
        const uint32_t* q_r0 = (const uint32_t*)(Qh + ((size_t)b * SEQ + q0 + g)     * 4096 + h * 128);
        const uint32_t* q_r1 = (const uint32_t*)(Qh + ((size_t)b * SEQ + q0 + g + 8) * 4096 + h * 128);
#pragma unroll
        for (int kc = 0; kc < 8; kc++) {
            qa[kc][0] = q_r0[kc * 8 + qc];
            qa[kc][1] = q_r1[kc * 8 + qc];
            qa[kc][2] = q_r0[kc * 8 + qc + 4];
            qa[kc][3] = q_r1[kc * 8 + qc + 4];
        }
    }

    float o[16][4];
#pragma unroll
    for (int n = 0; n < 16; n++)
#pragma unroll
        for (int j = 0; j < 4; j++) o[n][j] = 0.0f;
    float m0 = -1e30f, m1 = -1e30f, l0 = 0.0f, l1 = 0.0f;

    load_kv(0, 0);

    int buf = 0;
    for (int kt = 0; kt < NKT; kt++) {
        const int kb = kt * 64;
        asm volatile("cp.async.wait_group 0;" ::: "memory");
        __syncthreads();

        if (kt + 1 < NKT) load_kv(kt + 1, buf ^ 1);

        const uint32_t kS = s0 + buf * KVSTG;
        const uint32_t vS = kS + KVMAT;
        buf ^= 1;

        if (kb > q0 + 15) continue;

        float sreg[8][4];
#pragma unroll
        for (int j = 0; j < 8; j++)
            sreg[j][0] = sreg[j][1] = sreg[j][2] = sreg[j][3] = 0.0f;
#pragma unroll
        for (int kc = 0; kc < 8; kc++) {
#pragma unroll
            for (int j2 = 0; j2 < 4; j2++) {
                uint32_t r[4];
                ldsm4(r, kS + (j2 * 16 + k_row) * KVROW + kc * 32 + k_db);
                mma_f16(sreg[2 * j2],     qa[kc], r[0], r[1]);
                mma_f16(sreg[2 * j2 + 1], qa[kc], r[2], r[3]);
            }
        }

        if (kb + 63 > q0) {
#pragma unroll
            for (int j = 0; j < 8; j++) {
                int key0 = kb + j * 8 + 2 * qc;
                if (key0     > q0 + g)     sreg[j][0] = -1e30f;
                if (key0 + 1 > q0 + g)     sreg[j][1] = -1e30f;
                if (key0     > q0 + g + 8) sreg[j][2] = -1e30f;
                if (key0 + 1 > q0 + g + 8) sreg[j][3] = -1e30f;
            }
        }

        float mx0 = -1e30f, mx1 = -1e30f;
#pragma unroll
        for (int j = 0; j < 8; j++) {
            mx0 = fmaxf(mx0, fmaxf(sreg[j][0], sreg[j][1]));
            mx1 = fmaxf(mx1, fmaxf(sreg[j][2], sreg[j][3]));
        }
        mx0 = fmaxf(mx0, __shfl_xor_sync(0xffffffffu, mx0, 1));
        mx0 = fmaxf(mx0, __shfl_xor_sync(0xffffffffu, mx0, 2));
        mx1 = fmaxf(mx1, __shfl_xor_sync(0xffffffffu, mx1, 1));
        mx1 = fmaxf(mx1, __shfl_xor_sync(0xffffffffu, mx1, 2));
        float mn0 = fmaxf(m0, mx0), mn1 = fmaxf(m1, mx1);
        float f0 = __expf(m0 - mn0), f1 = __expf(m1 - mn1);
        m0 = mn0; m1 = mn1;

        float sum0 = 0.0f, sum1 = 0.0f;
#pragma unroll
        for (int j = 0; j < 8; j++) {
            sreg[j][0] = __expf(sreg[j][0] - mn0);
            sreg[j][1] = __expf(sreg[j][1] - mn0);
            sreg[j][2] = __expf(sreg[j][2] - mn1);
            sreg[j][3] = __expf(sreg[j][3] - mn1);
            sum0 += sreg[j][0] + sreg[j][1];
            sum1 += sreg[j][2] + sreg[j][3];
        }
        sum0 += __shfl_xor_sync(0xffffffffu, sum0, 1);
        sum0 += __shfl_xor_sync(0xffffffffu, sum0, 2);
        sum1 += __shfl_xor_sync(0xffffffffu, sum1, 1);
        sum1 += __shfl_xor_sync(0xffffffffu, sum1, 2);
        l0 = l0 * f0 + sum0;
        l1 = l1 * f1 + sum1;

#pragma unroll
        for (int n = 0; n < 16; n++) {
            o[n][0] *= f0; o[n][1] *= f0;
            o[n][2] *= f1; o[n][3] *= f1;
        }

        uint32_t pa[4][4];
#pragma unroll
        for (int kc = 0; kc < 4; kc++) {
            pa[kc][0] = pack_h2(sreg[2 * kc][0],     sreg[2 * kc][1]);
            pa[kc][1] = pack_h2(sreg[2 * kc][2],     sreg[2 * kc][3]);
            pa[kc][2] = pack_h2(sreg[2 * kc + 1][0], sreg[2 * kc + 1][1]);
            pa[kc][3] = pack_h2(sreg[2 * kc + 1][2], sreg[2 * kc + 1][3]);
        }

#pragma unroll
        for (int kc = 0; kc < 4; kc++) {
#pragma unroll
            for (int d0 = 0; d0 < 8; d0++) {
                uint32_t r[4];
                ldsm4t(r, vS + (kc * 16 + v_row) * KVROW + d0 * 32 + v_db);
                mma_f16(o[2 * d0],     pa[kc], r[0], r[1]);
                mma_f16(o[2 * d0 + 1], pa[kc], r[2], r[3]);
            }
        }
    }

    const float inv0 = 1.0f / l0;
    const float inv1 = 1.0f / l1;
    const size_t base0 = ((size_t)b * SEQ + q0 + g)     * 4096 + h * 128;
    const size_t base1 = ((size_t)b * SEQ + q0 + g + 8) * 4096 + h * 128;
#pragma unroll
    for (int n = 0; n < 16; n++) {
        *(__half2*)&O16[base0 + n * 8 + 2 * qc] =
            __floats2half2_rn(o[n][0] * inv0, o[n][1] * inv0);
        *(__half2*)&O16[base1 + n * 8 + 2 * qc] =
            __floats2half2_rn(o[n][2] * inv1, o[n][3] * inv1);
    }
}

// ---------------------------------------------------------------------------
extern "C" void kernel_launch(void* const* d_in, const int* in_sizes, int n_in,
                              void* d_out, int out_size)
{
    const float* x = (const float*)d_in[0];
    int off = (n_in >= 6 && in_sizes[1] <= 4) ? 2 : 1;
    const float* wq = (const float*)d_in[off + 0];
    const float* wk = (const float*)d_in[off + 1];
    const float* wv = (const float*)d_in[off + 2];
    const float* wo = (const float*)d_in[off + 3];
    float* out = (float*)d_out;

    __half *q, *k, *v;
    float *ct, *st;
    cudaGetSymbolAddress((void**)&q,  g_q);
    cudaGetSymbolAddress((void**)&k,  g_k);
    cudaGetSymbolAddress((void**)&v,  g_v);
    cudaGetSymbolAddress((void**)&ct, g_cos);
    cudaGetSymbolAddress((void**)&st, g_sin);

    __half *x16, *wq16, *wk16, *wv16, *wo16, *a16;
    cudaGetSymbolAddress((void**)&x16,  g_x16);
    cudaGetSymbolAddress((void**)&wq16, g_wq16);
    cudaGetSymbolAddress((void**)&wk16, g_wk16);
    cudaGetSymbolAddress((void**)&wv16, g_wv16);
    cudaGetSymbolAddress((void**)&wo16, g_wo16);
    cudaGetSymbolAddress((void**)&a16,  g_a16);

    cudaFuncSetAttribute(gemm_qkv, cudaFuncAttributeMaxDynamicSharedMemorySize, 3 * STAGE_SZ);
    cudaFuncSetAttribute(gemm_out, cudaFuncAttributeMaxDynamicSharedMemorySize, 3 * STAGE_SZ);
    cudaFuncSetAttribute(attn_tc,  cudaFuncAttributeMaxDynamicSharedMemorySize, ATTN_SMEM);

    const int n4 = DIM * DIM / 4;
    const int cgrid = (n4 + 255) / 256;

    const float SC   = 0.015625f;                        // 2^-6 (weights x64)
    const float SC_Q = SC * 0.08838834764831845f;        // fold 1/sqrt(128) into q

    // side stream for weight casts / rope table (fork-join inside capture)
    cudaStream_t s1;
    cudaStreamCreateWithFlags(&s1, cudaStreamNonBlocking);
    cudaEvent_t evF, evQKV, evO;
    cudaEventCreateWithFlags(&evF,   cudaEventDisableTiming);
    cudaEventCreateWithFlags(&evQKV, cudaEventDisableTiming);
    cudaEventCreateWithFlags(&evO,   cudaEventDisableTiming);

    cudaEventRecord(evF, 0);
    cudaStreamWaitEvent(s1, evF, 0);

    rope_table<<<(SEQ * (HD / 2) + 255) / 256, 256, 0, s1>>>(ct, st);
    split_wt<<<cgrid, 256, 0, s1>>>(wq, wq16, n4);
    split_wt<<<cgrid, 256, 0, s1>>>(wk, wk16, n4);
    split_wt<<<cgrid, 256, 0, s1>>>(wv, wv16, n4);
    cudaEventRecord(evQKV, s1);
    split_wt<<<cgrid, 256, 0, s1>>>(wo, wo16, n4);
    cudaEventRecord(evO, s1);

    split_act<<<cgrid, 256>>>(x, x16, n4);

    cudaStreamWaitEvent(0, evQKV, 0);
    gemm_qkv<<<dim3(96, 32), 256, 3 * STAGE_SZ>>>(x16, wq16, wk16, wv16,
                                                  q, k, v, SC_Q, SC, ct, st);

    attn_tc<<<dim3(SEQ / 128, NH, BSZ), 256, ATTN_SMEM>>>(q, k, v, a16);

    cudaStreamWaitEvent(0, evO, 0);
    gemm_out<<<dim3(32, 32), 256, 3 * STAGE_SZ>>>(a16, wo16, out, SC);
}